// round 16
// baseline (speedup 1.0000x reference)
#include <cuda_runtime.h>
#include <cuda_fp16.h>

#define N_USERS 40000
#define N_ITEMS 20000
#define NNZ     1000000
#define D       64
#define N_TOTAL (N_USERS + N_ITEMS)
#define EPS     1e-8f
#define NB_SCAT ((NNZ + 255) / 256)
#define NB_EMBU  ((N_USERS * 32 + 255) / 256)
#define FULL 0xffffffffu

// ---------------- device scratch ----------------
__device__ uint4 g_lin_u[N_ITEMS * 8];
__device__ uint4 g_lin_i[N_USERS * 8];
__device__ uint4 g_emb_u0[N_USERS * 8];
__device__ uint4 g_emb_u1[N_USERS * 8];
__device__ uint4 g_emb_i0[N_ITEMS * 8];
__device__ uint4 g_emb_i1[N_ITEMS * 8];
__device__ float g_inv_u[N_USERS];
__device__ float g_inv_i[N_ITEMS];
__device__ float g_w_u[NNZ];
__device__ float g_w_i[NNZ];
__device__ int2  g_pk_u[NNZ];
__device__ int2  g_pk_i[NNZ];
__device__ int   g_i_src_u[NNZ];
__device__ int   g_slot[NNZ];
__device__ int   g_u_ptr[N_USERS + 1];
__device__ int   g_i_ptr[N_ITEMS + 1];
__device__ int   g_i_cnt[N_ITEMS];

// ---------------- helpers ----------------
__device__ __forceinline__ void acc8(float2& a0, float2& a1, float2& a2, float2& a3,
                                     uint4 v, float w) {
    float2 b;
    b = __half22float2(*(__half2*)&v.x); a0.x = fmaf(w, b.x, a0.x); a0.y = fmaf(w, b.y, a0.y);
    b = __half22float2(*(__half2*)&v.y); a1.x = fmaf(w, b.x, a1.x); a1.y = fmaf(w, b.y, a1.y);
    b = __half22float2(*(__half2*)&v.z); a2.x = fmaf(w, b.x, a2.x); a2.y = fmaf(w, b.y, a2.y);
    b = __half22float2(*(__half2*)&v.w); a3.x = fmaf(w, b.x, a3.x); a3.y = fmaf(w, b.y, a3.y);
}
__device__ __forceinline__ float dot8(const float2& A0, const float2& A1,
                                      const float2& A2, const float2& A3, uint4 v) {
    float2 b;
    float d = 0.f;
    b = __half22float2(*(__half2*)&v.x); d = fmaf(A0.x, b.x, d); d = fmaf(A0.y, b.y, d);
    b = __half22float2(*(__half2*)&v.y); d = fmaf(A1.x, b.x, d); d = fmaf(A1.y, b.y, d);
    b = __half22float2(*(__half2*)&v.z); d = fmaf(A2.x, b.x, d); d = fmaf(A2.y, b.y, d);
    b = __half22float2(*(__half2*)&v.w); d = fmaf(A3.x, b.x, d); d = fmaf(A3.y, b.y, d);
    return d;
}
__device__ __forceinline__ uint4 pack8(float2 a0, float2 a1, float2 a2, float2 a3) {
    uint4 r;
    *(__half2*)&r.x = __floats2half2_rn(a0.x, a0.y);
    *(__half2*)&r.y = __floats2half2_rn(a1.x, a1.y);
    *(__half2*)&r.z = __floats2half2_rn(a2.x, a2.y);
    *(__half2*)&r.w = __floats2half2_rn(a3.x, a3.y);
    return r;
}
__device__ __forceinline__ void xor_reduce_groups(float2& a0, float2& a1, float2& a2, float2& a3) {
    #pragma unroll
    for (int o = 8; o <= 16; o <<= 1) {
        a0.x += __shfl_xor_sync(FULL, a0.x, o);
        a0.y += __shfl_xor_sync(FULL, a0.y, o);
        a1.x += __shfl_xor_sync(FULL, a1.x, o);
        a1.y += __shfl_xor_sync(FULL, a1.y, o);
        a2.x += __shfl_xor_sync(FULL, a2.x, o);
        a2.y += __shfl_xor_sync(FULL, a2.y, o);
        a3.x += __shfl_xor_sync(FULL, a3.x, o);
        a3.y += __shfl_xor_sync(FULL, a3.y, o);
    }
}
__device__ __forceinline__ void store_out(float* __restrict__ out, int r, int c,
                                          float2 a0, float2 a1, float2 a2, float2 a3,
                                          float scale) {
    float4* o = (float4*)(out + (size_t)r * D + c * 8);
    float4 o0 = o[0], o1 = o[1];
    o0.x = (o0.x + a0.x) * scale; o0.y = (o0.y + a0.y) * scale;
    o0.z = (o0.z + a1.x) * scale; o0.w = (o0.w + a1.y) * scale;
    o1.x = (o1.x + a2.x) * scale; o1.y = (o1.y + a2.y) * scale;
    o1.z = (o1.z + a3.x) * scale; o1.w = (o1.w + a3.y) * scale;
    o[0] = o0; o[1] = o1;
}

// batched gather-accumulate, full blocks software-pipelined (2 loads in flight).
__device__ __forceinline__ void gather_sum(const int* __restrict__ idxarr,
                                           const uint4* __restrict__ btab,
                                           int beg, int end, int lane, int g, int c,
                                           float2& a0, float2& a1, float2& a2, float2& a3) {
    int bs = beg;
    #pragma unroll 1
    for (; bs + 32 <= end; bs += 32) {
        int myidx = idxarr[bs + lane];
        int idx = __shfl_sync(FULL, myidx, g);
        uint4 v = btab[idx * 8 + c];
        #pragma unroll 1
        for (int kk = 4; kk < 32; kk += 4) {
            int idx2 = __shfl_sync(FULL, myidx, kk + g);
            uint4 v2 = btab[idx2 * 8 + c];       // next load in flight
            acc8(a0, a1, a2, a3, v, 1.0f);        // consume current
            v = v2;
        }
        acc8(a0, a1, a2, a3, v, 1.0f);
    }
    if (bs < end) {
        int n = end - bs;
        int myidx = (lane < n) ? idxarr[bs + lane] : 0;
        #pragma unroll 1
        for (int kk = 0; kk < n; kk += 4) {
            int k = kk + g;
            bool valid = k < n;
            int idx = __shfl_sync(FULL, myidx, k & 31);
            uint4 v = btab[idx * 8 + c];
            acc8(a0, a1, a2, a3, v, valid ? 1.0f : 0.0f);
        }
    }
}

// ---------------- K1: zero counts + user CSR ptr + fp16 conversion ----------------
__global__ void k_setup(const int* __restrict__ u_idx,
                        const float* __restrict__ user_linear,
                        const float* __restrict__ item_linear) {
    int t = blockIdx.x * blockDim.x + threadIdx.x;
    if (t < N_ITEMS) g_i_cnt[t] = 0;
    if (t <= N_USERS) {
        int lo = 0, hi = NNZ;
        while (lo < hi) { int mid = (lo + hi) >> 1; if (u_idx[mid] < t) lo = mid + 1; else hi = mid; }
        g_u_ptr[t] = lo;
    }
    const int NU = N_ITEMS * 8;
    const int NI = N_USERS * 8;
    if (t < NU) {
        const float4* s = (const float4*)user_linear;
        float4 x0 = s[2 * t], x1 = s[2 * t + 1];
        g_lin_u[t] = pack8(make_float2(x0.x, x0.y), make_float2(x0.z, x0.w),
                           make_float2(x1.x, x1.y), make_float2(x1.z, x1.w));
    } else if (t < NU + NI) {
        int k = t - NU;
        const float4* s = (const float4*)item_linear;
        float4 x0 = s[2 * k], x1 = s[2 * k + 1];
        g_lin_i[k] = pack8(make_float2(x0.x, x0.y), make_float2(x0.z, x0.w),
                           make_float2(x1.x, x1.y), make_float2(x1.z, x1.w));
    }
}

// ---------------- K2: item-degree count, capturing per-edge ranks ----------------
__global__ void k_count(const int* __restrict__ i_idx) {
    int e = blockIdx.x * blockDim.x + threadIdx.x;
    if (e < NNZ) g_slot[e] = atomicAdd(&g_i_cnt[i_idx[e]], 1);
}

// ---------------- K3: single-block vectorized exclusive scan ----------------
__global__ void __launch_bounds__(1024) k_scan1() {
    __shared__ int wsum[32];
    int tid = threadIdx.x, lane = tid & 31, wid = tid >> 5;
    const int4* cnt4 = (const int4*)g_i_cnt;
    int4* ptr4 = (int4*)g_i_ptr;
    int v[20];
    int s = 0;
    if (tid < 1000) {
        #pragma unroll
        for (int k = 0; k < 5; ++k) {
            int4 x = cnt4[tid * 5 + k];
            v[4*k+0] = s; s += x.x;
            v[4*k+1] = s; s += x.y;
            v[4*k+2] = s; s += x.z;
            v[4*k+3] = s; s += x.w;
        }
    }
    int t = s;
    #pragma unroll
    for (int o = 1; o < 32; o <<= 1) { int y = __shfl_up_sync(FULL, t, o); if (lane >= o) t += y; }
    if (lane == 31) wsum[wid] = t;
    __syncthreads();
    if (wid == 0) {
        int x = wsum[lane];
        #pragma unroll
        for (int o = 1; o < 32; o <<= 1) { int y = __shfl_up_sync(FULL, x, o); if (lane >= o) x += y; }
        wsum[lane] = x;
    }
    __syncthreads();
    int offset = (t - s) + (wid ? wsum[wid - 1] : 0);
    if (tid < 1000) {
        #pragma unroll
        for (int k = 0; k < 5; ++k) {
            ptr4[tid * 5 + k] = make_int4(offset + v[4*k], offset + v[4*k+1],
                                          offset + v[4*k+2], offset + v[4*k+3]);
        }
    }
    if (tid == 0) g_i_ptr[N_ITEMS] = NNZ;
}

// ---- K4: FUSED atomic-free scatter + user-side base embeddings (block-role split) ----
__global__ void __launch_bounds__(256) k_scat_embu(const int* __restrict__ u_idx,
                                                   const int* __restrict__ i_idx,
                                                   float* __restrict__ out) {
    if (blockIdx.x < NB_SCAT) {
        int e = blockIdx.x * 256 + threadIdx.x;
        if (e < NNZ) {
            int i = i_idx[e];
            int pos = g_i_ptr[i] + g_slot[e];
            g_i_src_u[pos] = u_idx[e];
            g_slot[e] = pos;
        }
        return;
    }
    int r = ((blockIdx.x - NB_SCAT) * 256 + threadIdx.x) >> 5;
    if (r >= N_USERS) return;
    int lane = threadIdx.x & 31, g = lane >> 3, c = lane & 7;
    int beg = g_u_ptr[r], end = g_u_ptr[r + 1];
    float2 a0 = {0,0}, a1 = {0,0}, a2 = {0,0}, a3 = {0,0};
    gather_sum(i_idx, g_lin_u, beg, end, lane, g, c, a0, a1, a2, a3);
    xor_reduce_groups(a0, a1, a2, a3);
    float ss = a0.x*a0.x + a0.y*a0.y + a1.x*a1.x + a1.y*a1.y
             + a2.x*a2.x + a2.y*a2.y + a3.x*a3.x + a3.y*a3.y;
    #pragma unroll
    for (int o = 1; o <= 4; o <<= 1) ss += __shfl_xor_sync(FULL, ss, o);
    if (lane == 0) g_inv_u[r] = 1.0f / fmaxf(sqrtf(ss), EPS);
    if (g == 0) {
        g_emb_u0[r * 8 + c] = pack8(a0, a1, a2, a3);
        float4* o = (float4*)(out + (size_t)r * D + c * 8);
        o[0] = make_float4(a0.x, a0.y, a1.x, a1.y);
        o[1] = make_float4(a2.x, a2.y, a3.x, a3.y);
    }
}

// ---------------- item-side base embeddings ----------------
__global__ void __launch_bounds__(256) k_emb_i(float* __restrict__ out) {
    int r = (blockIdx.x * blockDim.x + threadIdx.x) >> 5;
    if (r >= N_ITEMS) return;
    int lane = threadIdx.x & 31, g = lane >> 3, c = lane & 7;
    int beg = g_i_ptr[r], end = g_i_ptr[r + 1];
    float2 a0 = {0,0}, a1 = {0,0}, a2 = {0,0}, a3 = {0,0};
    gather_sum(g_i_src_u, g_lin_i, beg, end, lane, g, c, a0, a1, a2, a3);
    xor_reduce_groups(a0, a1, a2, a3);
    float ss = a0.x*a0.x + a0.y*a0.y + a1.x*a1.x + a1.y*a1.y
             + a2.x*a2.x + a2.y*a2.y + a3.x*a3.x + a3.y*a3.y;
    #pragma unroll
    for (int o = 1; o <= 4; o <<= 1) ss += __shfl_xor_sync(FULL, ss, o);
    if (lane == 0) g_inv_i[r] = 1.0f / fmaxf(sqrtf(ss), EPS);
    if (g == 0) {
        g_emb_i0[r * 8 + c] = pack8(a0, a1, a2, a3);
        float4* o = (float4*)(out + (size_t)(N_USERS + r) * D + c * 8);
        o[0] = make_float4(a0.x, a0.y, a1.x, a1.y);
        o[1] = make_float4(a2.x, a2.y, a3.x, a3.y);
    }
}

// ---- weights + u-norm + FUSED layer-1 user propagation + pk_u packing (warp per user) ----
__global__ void __launch_bounds__(256) k_weights(const int* __restrict__ i_idx,
                                                 float* __restrict__ out) {
    int u = (blockIdx.x * blockDim.x + threadIdx.x) >> 5;
    if (u >= N_USERS) return;
    int lane = threadIdx.x & 31, g = lane >> 3, c = lane & 7;
    int beg = g_u_ptr[u], end = g_u_ptr[u + 1];
    uint4 av = g_emb_u0[u * 8 + c];
    float2 A0 = __half22float2(*(__half2*)&av.x);
    float2 A1 = __half22float2(*(__half2*)&av.y);
    float2 A2 = __half22float2(*(__half2*)&av.z);
    float2 A3 = __half22float2(*(__half2*)&av.w);
    float invu = g_inv_u[u];
    float sum = 0.f;
    // pass 1: cosine weights — pipelined full blocks, then tail
    int bs = beg;
    #pragma unroll 1
    for (; bs + 32 <= end; bs += 32) {
        int myidx = i_idx[bs + lane];
        int icur = __shfl_sync(FULL, myidx, g);
        uint4 bv = g_emb_i0[icur * 8 + c];
        int kprev = 0;
        #pragma unroll 1
        for (int kk = 4; kk < 32; kk += 4) {
            int inext = __shfl_sync(FULL, myidx, kk + g);
            uint4 bvn = g_emb_i0[inext * 8 + c];
            float d = dot8(A0, A1, A2, A3, bv);
            #pragma unroll
            for (int o = 1; o <= 4; o <<= 1) d += __shfl_xor_sync(FULL, d, o);
            if (c == 0) {
                int e = bs + kprev + g;
                float s = d * invu * g_inv_i[icur];
                float w = fmaf(s, 0.5f, 0.5f);
                g_w_u[e] = w; g_w_i[g_slot[e]] = w; sum += w;
            }
            bv = bvn; icur = inext; kprev = kk;
        }
        {
            float d = dot8(A0, A1, A2, A3, bv);
            #pragma unroll
            for (int o = 1; o <= 4; o <<= 1) d += __shfl_xor_sync(FULL, d, o);
            if (c == 0) {
                int e = bs + 28 + g;
                float s = d * invu * g_inv_i[icur];
                float w = fmaf(s, 0.5f, 0.5f);
                g_w_u[e] = w; g_w_i[g_slot[e]] = w; sum += w;
            }
        }
    }
    if (bs < end) {
        int n = end - bs;
        int myidx = (lane < n) ? i_idx[bs + lane] : 0;
        #pragma unroll 1
        for (int kk = 0; kk < n; kk += 4) {
            int k = kk + g;
            bool valid = k < n;
            int i = __shfl_sync(FULL, myidx, k & 31);
            uint4 bv = g_emb_i0[i * 8 + c];
            float d = dot8(A0, A1, A2, A3, bv);
            #pragma unroll
            for (int o = 1; o <= 4; o <<= 1) d += __shfl_xor_sync(FULL, d, o);
            if (c == 0 && valid) {
                int e = bs + k;
                float s = d * invu * g_inv_i[i];
                float w = fmaf(s, 0.5f, 0.5f);
                g_w_u[e] = w; g_w_i[g_slot[e]] = w; sum += w;
            }
        }
    }
    sum += __shfl_xor_sync(FULL, sum, 8);
    sum += __shfl_xor_sync(FULL, sum, 16);
    float invd = 1.0f / (sum + 1e-7f);
    invd = __shfl_sync(FULL, invd, 0);
    __syncwarp();
    __threadfence_block();
    // pass 2: layer-1 user propagation + pk_u packing — pipelined full blocks, then tail
    float2 a0 = {0,0}, a1 = {0,0}, a2 = {0,0}, a3 = {0,0};
    bs = beg;
    #pragma unroll 1
    for (; bs + 32 <= end; bs += 32) {
        int myidx = i_idx[bs + lane];
        float myw = g_w_u[bs + lane] * invd;
        g_pk_u[bs + lane] = make_int2(myidx, __float_as_int(myw));
        int idx = __shfl_sync(FULL, myidx, g);
        float wcur = __shfl_sync(FULL, myw, g);
        uint4 v = g_emb_i0[idx * 8 + c];
        #pragma unroll 1
        for (int kk = 4; kk < 32; kk += 4) {
            int idx2 = __shfl_sync(FULL, myidx, kk + g);
            float w2 = __shfl_sync(FULL, myw, kk + g);
            uint4 v2 = g_emb_i0[idx2 * 8 + c];
            acc8(a0, a1, a2, a3, v, wcur);
            v = v2; wcur = w2;
        }
        acc8(a0, a1, a2, a3, v, wcur);
    }
    if (bs < end) {
        int n = end - bs;
        int myidx = (lane < n) ? i_idx[bs + lane] : 0;
        float myw = (lane < n) ? g_w_u[bs + lane] * invd : 0.0f;
        if (lane < n) g_pk_u[bs + lane] = make_int2(myidx, __float_as_int(myw));
        #pragma unroll 1
        for (int kk = 0; kk < n; kk += 4) {
            int k = kk + g;
            bool valid = k < n;
            int i = __shfl_sync(FULL, myidx, k & 31);
            float wn = __shfl_sync(FULL, myw, k & 31);
            uint4 v = g_emb_i0[i * 8 + c];
            acc8(a0, a1, a2, a3, v, valid ? wn : 0.0f);
        }
    }
    xor_reduce_groups(a0, a1, a2, a3);
    if (g == 0) {
        g_emb_u1[u * 8 + c] = pack8(a0, a1, a2, a3);
        store_out(out, u, c, a0, a1, a2, a3, 1.0f);
    }
}

// ---- i-norm + FUSED layer-1 item propagation + pk_i packing (warp per item) ----
__global__ void __launch_bounds__(256) k_norm_i(float* __restrict__ out) {
    int i = (blockIdx.x * blockDim.x + threadIdx.x) >> 5;
    if (i >= N_ITEMS) return;
    int lane = threadIdx.x & 31, g = lane >> 3, c = lane & 7;
    int beg = g_i_ptr[i], end = g_i_ptr[i + 1];
    float s = 0.f;
    for (int p = beg + lane; p < end; p += 32) s += g_w_i[p];
    #pragma unroll
    for (int o = 16; o; o >>= 1) s += __shfl_xor_sync(FULL, s, o);
    float invd = 1.0f / (s + 1e-7f);
    float2 a0 = {0,0}, a1 = {0,0}, a2 = {0,0}, a3 = {0,0};
    int bs = beg;
    #pragma unroll 1
    for (; bs + 32 <= end; bs += 32) {
        int myidx = g_i_src_u[bs + lane];
        float myw = g_w_i[bs + lane] * invd;
        g_pk_i[bs + lane] = make_int2(myidx, __float_as_int(myw));
        int idx = __shfl_sync(FULL, myidx, g);
        float wcur = __shfl_sync(FULL, myw, g);
        uint4 v = g_emb_u0[idx * 8 + c];
        #pragma unroll 1
        for (int kk = 4; kk < 32; kk += 4) {
            int idx2 = __shfl_sync(FULL, myidx, kk + g);
            float w2 = __shfl_sync(FULL, myw, kk + g);
            uint4 v2 = g_emb_u0[idx2 * 8 + c];
            acc8(a0, a1, a2, a3, v, wcur);
            v = v2; wcur = w2;
        }
        acc8(a0, a1, a2, a3, v, wcur);
    }
    if (bs < end) {
        int n = end - bs;
        int myidx = (lane < n) ? g_i_src_u[bs + lane] : 0;
        float myw = (lane < n) ? g_w_i[bs + lane] * invd : 0.0f;
        if (lane < n) g_pk_i[bs + lane] = make_int2(myidx, __float_as_int(myw));
        #pragma unroll 1
        for (int kk = 0; kk < n; kk += 4) {
            int k = kk + g;
            bool valid = k < n;
            int uu = __shfl_sync(FULL, myidx, k & 31);
            float wn = __shfl_sync(FULL, myw, k & 31);
            uint4 v = g_emb_u0[uu * 8 + c];
            acc8(a0, a1, a2, a3, v, valid ? wn : 0.0f);
        }
    }
    xor_reduce_groups(a0, a1, a2, a3);
    if (g == 0) {
        g_emb_i1[i * 8 + c] = pack8(a0, a1, a2, a3);
        store_out(out, N_USERS + i, c, a0, a1, a2, a3, 1.0f);
    }
}

// ---------------- propagation layers 2,3 ----------------
__global__ void __launch_bounds__(256) k_prop(float* __restrict__ out, int flip,
                                              float scale, int write_dst) {
    int r = (blockIdx.x * blockDim.x + threadIdx.x) >> 5;
    if (r >= N_TOTAL) return;
    int lane = threadIdx.x & 31, g = lane >> 3, c = lane & 7;
    const int2* __restrict__ pk;
    const uint4* __restrict__ src;
    uint4* __restrict__ dst;
    int beg, end, row;
    if (r < N_USERS) {
        row = r; pk = g_pk_u;
        src = flip ? g_emb_i1 : g_emb_i0;
        dst = flip ? g_emb_u0 : g_emb_u1;
        beg = g_u_ptr[r]; end = g_u_ptr[r + 1];
    } else {
        row = r - N_USERS; pk = g_pk_i;
        src = flip ? g_emb_u1 : g_emb_u0;
        dst = flip ? g_emb_i0 : g_emb_i1;
        beg = g_i_ptr[row]; end = g_i_ptr[row + 1];
    }
    float2 a0 = {0,0}, a1 = {0,0}, a2 = {0,0}, a3 = {0,0};
    int bs = beg;
    #pragma unroll 1
    for (; bs + 32 <= end; bs += 32) {
        int2 myp = pk[bs + lane];
        int idx = __shfl_sync(FULL, myp.x, g);
        float wcur = __int_as_float(__shfl_sync(FULL, myp.y, g));
        uint4 v = src[idx * 8 + c];
        #pragma unroll 1
        for (int kk = 4; kk < 32; kk += 4) {
            int idx2 = __shfl_sync(FULL, myp.x, kk + g);
            float w2 = __int_as_float(__shfl_sync(FULL, myp.y, kk + g));
            uint4 v2 = src[idx2 * 8 + c];
            acc8(a0, a1, a2, a3, v, wcur);
            v = v2; wcur = w2;
        }
        acc8(a0, a1, a2, a3, v, wcur);
    }
    if (bs < end) {
        int n = end - bs;
        int2 myp = (lane < n) ? pk[bs + lane] : make_int2(0, 0);
        #pragma unroll 1
        for (int kk = 0; kk < n; kk += 4) {
            int k = kk + g;
            bool valid = k < n;
            int idx = __shfl_sync(FULL, myp.x, k & 31);
            float wn = __int_as_float(__shfl_sync(FULL, myp.y, k & 31));
            uint4 v = src[idx * 8 + c];
            acc8(a0, a1, a2, a3, v, valid ? wn : 0.0f);
        }
    }
    xor_reduce_groups(a0, a1, a2, a3);
    if (g == 0) {
        if (write_dst) dst[row * 8 + c] = pack8(a0, a1, a2, a3);
        store_out(out, r, c, a0, a1, a2, a3, scale);
    }
}

// ---------------- launch ----------------
extern "C" void kernel_launch(void* const* d_in, const int* in_sizes, int n_in,
                              void* d_out, int out_size) {
    const float* user_linear = (const float*)d_in[0];
    const float* item_linear = (const float*)d_in[1];
    const int*   u_idx       = (const int*)d_in[2];
    const int*   i_idx       = (const int*)d_in[3];
    float* out = (float*)d_out;

    int setup_threads = (N_USERS + N_ITEMS) * 8;
    k_setup<<<(setup_threads + 255) / 256, 256>>>(u_idx, user_linear, item_linear);
    k_count<<<(NNZ + 255) / 256, 256>>>(i_idx);
    k_scan1<<<1, 1024>>>();
    // fused: scatter (latency-bound) + user-side embeddings (BW-bound)
    k_scat_embu<<<NB_SCAT + NB_EMBU, 256>>>(u_idx, i_idx, out);
    k_emb_i<<<(N_ITEMS * 32 + 255) / 256, 256>>>(out);

    k_weights<<<(N_USERS * 32 + 255) / 256, 256>>>(i_idx, out);
    k_norm_i<<<(N_ITEMS * 32 + 255) / 256, 256>>>(out);

    k_prop<<<(N_TOTAL * 32 + 255) / 256, 256>>>(out, 1, 1.0f, 1);
    k_prop<<<(N_TOTAL * 32 + 255) / 256, 256>>>(out, 0, 0.25f, 0);
}

// round 17
// speedup vs baseline: 1.0578x; 1.0578x over previous
#include <cuda_runtime.h>
#include <cuda_fp16.h>

#define N_USERS 40000
#define N_ITEMS 20000
#define NNZ     1000000
#define D       64
#define N_TOTAL (N_USERS + N_ITEMS)
#define EPS     1e-8f
#define NB_SCAT ((NNZ + 255) / 256)
#define NB_EMBU  ((N_USERS * 32 + 255) / 256)
#define FULL 0xffffffffu

// ---------------- device scratch ----------------
__device__ uint4 g_lin_u[N_ITEMS * 8];
__device__ uint4 g_lin_i[N_USERS * 8];
__device__ uint4 g_emb_u0[N_USERS * 8];
__device__ uint4 g_emb_u1[N_USERS * 8];
__device__ uint4 g_emb_i0[N_ITEMS * 8];
__device__ uint4 g_emb_i1[N_ITEMS * 8];
__device__ float g_inv_u[N_USERS];
__device__ float g_inv_i[N_ITEMS];
__device__ float g_w_u[NNZ];
__device__ float g_w_i[NNZ];
__device__ int2  g_pk_u[NNZ];
__device__ int2  g_pk_i[NNZ];
__device__ int   g_i_src_u[NNZ];
__device__ int   g_slot[NNZ];     // phase 1: rank within item segment; phase 2: final slot
__device__ int   g_u_ptr[N_USERS + 1];
__device__ int   g_i_ptr[N_ITEMS + 1];
__device__ int   g_i_cnt[N_ITEMS];

// ---------------- helpers ----------------
__device__ __forceinline__ void acc8(float2& a0, float2& a1, float2& a2, float2& a3,
                                     uint4 v, float w) {
    float2 b;
    b = __half22float2(*(__half2*)&v.x); a0.x = fmaf(w, b.x, a0.x); a0.y = fmaf(w, b.y, a0.y);
    b = __half22float2(*(__half2*)&v.y); a1.x = fmaf(w, b.x, a1.x); a1.y = fmaf(w, b.y, a1.y);
    b = __half22float2(*(__half2*)&v.z); a2.x = fmaf(w, b.x, a2.x); a2.y = fmaf(w, b.y, a2.y);
    b = __half22float2(*(__half2*)&v.w); a3.x = fmaf(w, b.x, a3.x); a3.y = fmaf(w, b.y, a3.y);
}
__device__ __forceinline__ uint4 pack8(float2 a0, float2 a1, float2 a2, float2 a3) {
    uint4 r;
    *(__half2*)&r.x = __floats2half2_rn(a0.x, a0.y);
    *(__half2*)&r.y = __floats2half2_rn(a1.x, a1.y);
    *(__half2*)&r.z = __floats2half2_rn(a2.x, a2.y);
    *(__half2*)&r.w = __floats2half2_rn(a3.x, a3.y);
    return r;
}
__device__ __forceinline__ void xor_reduce_groups(float2& a0, float2& a1, float2& a2, float2& a3) {
    #pragma unroll
    for (int o = 8; o <= 16; o <<= 1) {
        a0.x += __shfl_xor_sync(FULL, a0.x, o);
        a0.y += __shfl_xor_sync(FULL, a0.y, o);
        a1.x += __shfl_xor_sync(FULL, a1.x, o);
        a1.y += __shfl_xor_sync(FULL, a1.y, o);
        a2.x += __shfl_xor_sync(FULL, a2.x, o);
        a2.y += __shfl_xor_sync(FULL, a2.y, o);
        a3.x += __shfl_xor_sync(FULL, a3.x, o);
        a3.y += __shfl_xor_sync(FULL, a3.y, o);
    }
}
__device__ __forceinline__ void store_out(float* __restrict__ out, int r, int c,
                                          float2 a0, float2 a1, float2 a2, float2 a3,
                                          float scale) {
    float4* o = (float4*)(out + (size_t)r * D + c * 8);
    float4 o0 = o[0], o1 = o[1];
    o0.x = (o0.x + a0.x) * scale; o0.y = (o0.y + a0.y) * scale;
    o0.z = (o0.z + a1.x) * scale; o0.w = (o0.w + a1.y) * scale;
    o1.x = (o1.x + a2.x) * scale; o1.y = (o1.y + a2.y) * scale;
    o1.z = (o1.z + a3.x) * scale; o1.w = (o1.w + a3.y) * scale;
    o[0] = o0; o[1] = o1;
}

// batched gather-accumulate, full blocks software-pipelined (2 loads in flight).
// Pipelining is ONLY used here (plain-accumulate body) — it regressed when
// applied to the dot/weight-carrying loops (R16 lesson).
__device__ __forceinline__ void gather_sum(const int* __restrict__ idxarr,
                                           const uint4* __restrict__ btab,
                                           int beg, int end, int lane, int g, int c,
                                           float2& a0, float2& a1, float2& a2, float2& a3) {
    int bs = beg;
    #pragma unroll 1
    for (; bs + 32 <= end; bs += 32) {
        int myidx = idxarr[bs + lane];
        int idx = __shfl_sync(FULL, myidx, g);
        uint4 v = btab[idx * 8 + c];
        #pragma unroll 1
        for (int kk = 4; kk < 32; kk += 4) {
            int idx2 = __shfl_sync(FULL, myidx, kk + g);
            uint4 v2 = btab[idx2 * 8 + c];       // next load in flight
            acc8(a0, a1, a2, a3, v, 1.0f);        // consume current
            v = v2;
        }
        acc8(a0, a1, a2, a3, v, 1.0f);
    }
    if (bs < end) {
        int n = end - bs;
        int myidx = (lane < n) ? idxarr[bs + lane] : 0;
        #pragma unroll 1
        for (int kk = 0; kk < n; kk += 4) {
            int k = kk + g;
            bool valid = k < n;
            int idx = __shfl_sync(FULL, myidx, k & 31);
            uint4 v = btab[idx * 8 + c];
            acc8(a0, a1, a2, a3, v, valid ? 1.0f : 0.0f);
        }
    }
}

// ---------------- K1: zero counts + user CSR ptr + fp16 conversion ----------------
__global__ void k_setup(const int* __restrict__ u_idx,
                        const float* __restrict__ user_linear,
                        const float* __restrict__ item_linear) {
    int t = blockIdx.x * blockDim.x + threadIdx.x;
    if (t < N_ITEMS) g_i_cnt[t] = 0;
    if (t <= N_USERS) {
        int lo = 0, hi = NNZ;
        while (lo < hi) { int mid = (lo + hi) >> 1; if (u_idx[mid] < t) lo = mid + 1; else hi = mid; }
        g_u_ptr[t] = lo;
    }
    const int NU = N_ITEMS * 8;
    const int NI = N_USERS * 8;
    if (t < NU) {
        const float4* s = (const float4*)user_linear;
        float4 x0 = s[2 * t], x1 = s[2 * t + 1];
        g_lin_u[t] = pack8(make_float2(x0.x, x0.y), make_float2(x0.z, x0.w),
                           make_float2(x1.x, x1.y), make_float2(x1.z, x1.w));
    } else if (t < NU + NI) {
        int k = t - NU;
        const float4* s = (const float4*)item_linear;
        float4 x0 = s[2 * k], x1 = s[2 * k + 1];
        g_lin_i[k] = pack8(make_float2(x0.x, x0.y), make_float2(x0.z, x0.w),
                           make_float2(x1.x, x1.y), make_float2(x1.z, x1.w));
    }
}

// ---------------- K2: item-degree count, capturing per-edge ranks ----------------
__global__ void k_count(const int* __restrict__ i_idx) {
    int e = blockIdx.x * blockDim.x + threadIdx.x;
    if (e < NNZ) g_slot[e] = atomicAdd(&g_i_cnt[i_idx[e]], 1);
}

// ---------------- K3: single-block vectorized exclusive scan ----------------
__global__ void __launch_bounds__(1024) k_scan1() {
    __shared__ int wsum[32];
    int tid = threadIdx.x, lane = tid & 31, wid = tid >> 5;
    const int4* cnt4 = (const int4*)g_i_cnt;
    int4* ptr4 = (int4*)g_i_ptr;
    int v[20];
    int s = 0;
    if (tid < 1000) {
        #pragma unroll
        for (int k = 0; k < 5; ++k) {
            int4 x = cnt4[tid * 5 + k];
            v[4*k+0] = s; s += x.x;
            v[4*k+1] = s; s += x.y;
            v[4*k+2] = s; s += x.z;
            v[4*k+3] = s; s += x.w;
        }
    }
    int t = s;
    #pragma unroll
    for (int o = 1; o < 32; o <<= 1) { int y = __shfl_up_sync(FULL, t, o); if (lane >= o) t += y; }
    if (lane == 31) wsum[wid] = t;
    __syncthreads();
    if (wid == 0) {
        int x = wsum[lane];
        #pragma unroll
        for (int o = 1; o < 32; o <<= 1) { int y = __shfl_up_sync(FULL, x, o); if (lane >= o) x += y; }
        wsum[lane] = x;
    }
    __syncthreads();
    int offset = (t - s) + (wid ? wsum[wid - 1] : 0);
    if (tid < 1000) {
        #pragma unroll
        for (int k = 0; k < 5; ++k) {
            ptr4[tid * 5 + k] = make_int4(offset + v[4*k], offset + v[4*k+1],
                                          offset + v[4*k+2], offset + v[4*k+3]);
        }
    }
    if (tid == 0) g_i_ptr[N_ITEMS] = NNZ;
}

// ---- K4: FUSED atomic-free scatter + user-side base embeddings (block-role split) ----
__global__ void __launch_bounds__(256) k_scat_embu(const int* __restrict__ u_idx,
                                                   const int* __restrict__ i_idx,
                                                   float* __restrict__ out) {
    if (blockIdx.x < NB_SCAT) {
        int e = blockIdx.x * 256 + threadIdx.x;
        if (e < NNZ) {
            int i = i_idx[e];
            int pos = g_i_ptr[i] + g_slot[e];
            g_i_src_u[pos] = u_idx[e];
            g_slot[e] = pos;
        }
        return;
    }
    int r = ((blockIdx.x - NB_SCAT) * 256 + threadIdx.x) >> 5;
    if (r >= N_USERS) return;
    int lane = threadIdx.x & 31, g = lane >> 3, c = lane & 7;
    int beg = g_u_ptr[r], end = g_u_ptr[r + 1];
    float2 a0 = {0,0}, a1 = {0,0}, a2 = {0,0}, a3 = {0,0};
    gather_sum(i_idx, g_lin_u, beg, end, lane, g, c, a0, a1, a2, a3);
    xor_reduce_groups(a0, a1, a2, a3);
    float ss = a0.x*a0.x + a0.y*a0.y + a1.x*a1.x + a1.y*a1.y
             + a2.x*a2.x + a2.y*a2.y + a3.x*a3.x + a3.y*a3.y;
    #pragma unroll
    for (int o = 1; o <= 4; o <<= 1) ss += __shfl_xor_sync(FULL, ss, o);
    if (lane == 0) g_inv_u[r] = 1.0f / fmaxf(sqrtf(ss), EPS);
    if (g == 0) {
        g_emb_u0[r * 8 + c] = pack8(a0, a1, a2, a3);
        float4* o = (float4*)(out + (size_t)r * D + c * 8);
        o[0] = make_float4(a0.x, a0.y, a1.x, a1.y);
        o[1] = make_float4(a2.x, a2.y, a3.x, a3.y);
    }
}

// ---------------- item-side base embeddings ----------------
__global__ void __launch_bounds__(256) k_emb_i(float* __restrict__ out) {
    int r = (blockIdx.x * blockDim.x + threadIdx.x) >> 5;
    if (r >= N_ITEMS) return;
    int lane = threadIdx.x & 31, g = lane >> 3, c = lane & 7;
    int beg = g_i_ptr[r], end = g_i_ptr[r + 1];
    float2 a0 = {0,0}, a1 = {0,0}, a2 = {0,0}, a3 = {0,0};
    gather_sum(g_i_src_u, g_lin_i, beg, end, lane, g, c, a0, a1, a2, a3);
    xor_reduce_groups(a0, a1, a2, a3);
    float ss = a0.x*a0.x + a0.y*a0.y + a1.x*a1.x + a1.y*a1.y
             + a2.x*a2.x + a2.y*a2.y + a3.x*a3.x + a3.y*a3.y;
    #pragma unroll
    for (int o = 1; o <= 4; o <<= 1) ss += __shfl_xor_sync(FULL, ss, o);
    if (lane == 0) g_inv_i[r] = 1.0f / fmaxf(sqrtf(ss), EPS);
    if (g == 0) {
        g_emb_i0[r * 8 + c] = pack8(a0, a1, a2, a3);
        float4* o = (float4*)(out + (size_t)(N_USERS + r) * D + c * 8);
        o[0] = make_float4(a0.x, a0.y, a1.x, a1.y);
        o[1] = make_float4(a2.x, a2.y, a3.x, a3.y);
    }
}

// ---- weights + u-norm + FUSED layer-1 user propagation + pk_u packing (warp per user) ----
__global__ void __launch_bounds__(256) k_weights(const int* __restrict__ i_idx,
                                                 float* __restrict__ out) {
    int u = (blockIdx.x * blockDim.x + threadIdx.x) >> 5;
    if (u >= N_USERS) return;
    int lane = threadIdx.x & 31, g = lane >> 3, c = lane & 7;
    int beg = g_u_ptr[u], end = g_u_ptr[u + 1];
    uint4 av = g_emb_u0[u * 8 + c];
    float2 A0 = __half22float2(*(__half2*)&av.x);
    float2 A1 = __half22float2(*(__half2*)&av.y);
    float2 A2 = __half22float2(*(__half2*)&av.z);
    float2 A3 = __half22float2(*(__half2*)&av.w);
    float invu = g_inv_u[u];
    float sum = 0.f;
    // pass 1: cosine weights — full blocks unpredicated, then tail
    int bs = beg;
    #pragma unroll 1
    for (; bs + 32 <= end; bs += 32) {
        int myidx = i_idx[bs + lane];
        #pragma unroll 1
        for (int kk = 0; kk < 32; kk += 4) {
            int i = __shfl_sync(FULL, myidx, kk + g);
            uint4 bv = g_emb_i0[i * 8 + c];
            float2 b;
            float d = 0.f;
            b = __half22float2(*(__half2*)&bv.x); d = fmaf(A0.x, b.x, d); d = fmaf(A0.y, b.y, d);
            b = __half22float2(*(__half2*)&bv.y); d = fmaf(A1.x, b.x, d); d = fmaf(A1.y, b.y, d);
            b = __half22float2(*(__half2*)&bv.z); d = fmaf(A2.x, b.x, d); d = fmaf(A2.y, b.y, d);
            b = __half22float2(*(__half2*)&bv.w); d = fmaf(A3.x, b.x, d); d = fmaf(A3.y, b.y, d);
            #pragma unroll
            for (int o = 1; o <= 4; o <<= 1) d += __shfl_xor_sync(FULL, d, o);
            if (c == 0) {
                int e = bs + kk + g;
                float s = d * invu * g_inv_i[i];
                float w = fmaf(s, 0.5f, 0.5f);
                g_w_u[e] = w; g_w_i[g_slot[e]] = w; sum += w;
            }
        }
    }
    if (bs < end) {
        int n = end - bs;
        int myidx = (lane < n) ? i_idx[bs + lane] : 0;
        #pragma unroll 1
        for (int kk = 0; kk < n; kk += 4) {
            int k = kk + g;
            bool valid = k < n;
            int i = __shfl_sync(FULL, myidx, k & 31);
            uint4 bv = g_emb_i0[i * 8 + c];
            float2 b;
            float d = 0.f;
            b = __half22float2(*(__half2*)&bv.x); d = fmaf(A0.x, b.x, d); d = fmaf(A0.y, b.y, d);
            b = __half22float2(*(__half2*)&bv.y); d = fmaf(A1.x, b.x, d); d = fmaf(A1.y, b.y, d);
            b = __half22float2(*(__half2*)&bv.z); d = fmaf(A2.x, b.x, d); d = fmaf(A2.y, b.y, d);
            b = __half22float2(*(__half2*)&bv.w); d = fmaf(A3.x, b.x, d); d = fmaf(A3.y, b.y, d);
            #pragma unroll
            for (int o = 1; o <= 4; o <<= 1) d += __shfl_xor_sync(FULL, d, o);
            if (c == 0 && valid) {
                int e = bs + k;
                float s = d * invu * g_inv_i[i];
                float w = fmaf(s, 0.5f, 0.5f);
                g_w_u[e] = w; g_w_i[g_slot[e]] = w; sum += w;
            }
        }
    }
    sum += __shfl_xor_sync(FULL, sum, 8);
    sum += __shfl_xor_sync(FULL, sum, 16);
    float invd = 1.0f / (sum + 1e-7f);
    invd = __shfl_sync(FULL, invd, 0);
    __syncwarp();
    __threadfence_block();
    // pass 2: layer-1 user propagation + pk_u packing — full blocks, then tail
    float2 a0 = {0,0}, a1 = {0,0}, a2 = {0,0}, a3 = {0,0};
    bs = beg;
    #pragma unroll 1
    for (; bs + 32 <= end; bs += 32) {
        int myidx = i_idx[bs + lane];
        float myw = g_w_u[bs + lane] * invd;
        g_pk_u[bs + lane] = make_int2(myidx, __float_as_int(myw));
        #pragma unroll 1
        for (int kk = 0; kk < 32; kk += 4) {
            int i = __shfl_sync(FULL, myidx, kk + g);
            float wn = __shfl_sync(FULL, myw, kk + g);
            uint4 v = g_emb_i0[i * 8 + c];
            acc8(a0, a1, a2, a3, v, wn);
        }
    }
    if (bs < end) {
        int n = end - bs;
        int myidx = (lane < n) ? i_idx[bs + lane] : 0;
        float myw = (lane < n) ? g_w_u[bs + lane] * invd : 0.0f;
        if (lane < n) g_pk_u[bs + lane] = make_int2(myidx, __float_as_int(myw));
        #pragma unroll 1
        for (int kk = 0; kk < n; kk += 4) {
            int k = kk + g;
            bool valid = k < n;
            int i = __shfl_sync(FULL, myidx, k & 31);
            float wn = __shfl_sync(FULL, myw, k & 31);
            uint4 v = g_emb_i0[i * 8 + c];
            acc8(a0, a1, a2, a3, v, valid ? wn : 0.0f);
        }
    }
    xor_reduce_groups(a0, a1, a2, a3);
    if (g == 0) {
        g_emb_u1[u * 8 + c] = pack8(a0, a1, a2, a3);
        store_out(out, u, c, a0, a1, a2, a3, 1.0f);
    }
}

// ---- i-norm + FUSED layer-1 item propagation + pk_i packing (warp per item) ----
__global__ void __launch_bounds__(256) k_norm_i(float* __restrict__ out) {
    int i = (blockIdx.x * blockDim.x + threadIdx.x) >> 5;
    if (i >= N_ITEMS) return;
    int lane = threadIdx.x & 31, g = lane >> 3, c = lane & 7;
    int beg = g_i_ptr[i], end = g_i_ptr[i + 1];
    float s = 0.f;
    for (int p = beg + lane; p < end; p += 32) s += g_w_i[p];
    #pragma unroll
    for (int o = 16; o; o >>= 1) s += __shfl_xor_sync(FULL, s, o);
    float invd = 1.0f / (s + 1e-7f);
    float2 a0 = {0,0}, a1 = {0,0}, a2 = {0,0}, a3 = {0,0};
    int bs = beg;
    #pragma unroll 1
    for (; bs + 32 <= end; bs += 32) {
        int myidx = g_i_src_u[bs + lane];
        float myw = g_w_i[bs + lane] * invd;
        g_pk_i[bs + lane] = make_int2(myidx, __float_as_int(myw));
        #pragma unroll 1
        for (int kk = 0; kk < 32; kk += 4) {
            int uu = __shfl_sync(FULL, myidx, kk + g);
            float wn = __shfl_sync(FULL, myw, kk + g);
            uint4 v = g_emb_u0[uu * 8 + c];
            acc8(a0, a1, a2, a3, v, wn);
        }
    }
    if (bs < end) {
        int n = end - bs;
        int myidx = (lane < n) ? g_i_src_u[bs + lane] : 0;
        float myw = (lane < n) ? g_w_i[bs + lane] * invd : 0.0f;
        if (lane < n) g_pk_i[bs + lane] = make_int2(myidx, __float_as_int(myw));
        #pragma unroll 1
        for (int kk = 0; kk < n; kk += 4) {
            int k = kk + g;
            bool valid = k < n;
            int uu = __shfl_sync(FULL, myidx, k & 31);
            float wn = __shfl_sync(FULL, myw, k & 31);
            uint4 v = g_emb_u0[uu * 8 + c];
            acc8(a0, a1, a2, a3, v, valid ? wn : 0.0f);
        }
    }
    xor_reduce_groups(a0, a1, a2, a3);
    if (g == 0) {
        g_emb_i1[i * 8 + c] = pack8(a0, a1, a2, a3);
        store_out(out, N_USERS + i, c, a0, a1, a2, a3, 1.0f);
    }
}

// ---------------- propagation layers 2,3 ----------------
__global__ void __launch_bounds__(256) k_prop(float* __restrict__ out, int flip,
                                              float scale, int write_dst) {
    int r = (blockIdx.x * blockDim.x + threadIdx.x) >> 5;
    if (r >= N_TOTAL) return;
    int lane = threadIdx.x & 31, g = lane >> 3, c = lane & 7;
    const int2* __restrict__ pk;
    const uint4* __restrict__ src;
    uint4* __restrict__ dst;
    int beg, end, row;
    if (r < N_USERS) {
        row = r; pk = g_pk_u;
        src = flip ? g_emb_i1 : g_emb_i0;
        dst = flip ? g_emb_u0 : g_emb_u1;
        beg = g_u_ptr[r]; end = g_u_ptr[r + 1];
    } else {
        row = r - N_USERS; pk = g_pk_i;
        src = flip ? g_emb_u1 : g_emb_u0;
        dst = flip ? g_emb_i0 : g_emb_i1;
        beg = g_i_ptr[row]; end = g_i_ptr[row + 1];
    }
    float2 a0 = {0,0}, a1 = {0,0}, a2 = {0,0}, a3 = {0,0};
    int bs = beg;
    #pragma unroll 1
    for (; bs + 32 <= end; bs += 32) {
        int2 myp = pk[bs + lane];
        #pragma unroll 1
        for (int kk = 0; kk < 32; kk += 4) {
            int idx = __shfl_sync(FULL, myp.x, kk + g);
            float wn = __int_as_float(__shfl_sync(FULL, myp.y, kk + g));
            uint4 v = src[idx * 8 + c];
            acc8(a0, a1, a2, a3, v, wn);
        }
    }
    if (bs < end) {
        int n = end - bs;
        int2 myp = (lane < n) ? pk[bs + lane] : make_int2(0, 0);
        #pragma unroll 1
        for (int kk = 0; kk < n; kk += 4) {
            int k = kk + g;
            bool valid = k < n;
            int idx = __shfl_sync(FULL, myp.x, k & 31);
            float wn = __int_as_float(__shfl_sync(FULL, myp.y, k & 31));
            uint4 v = src[idx * 8 + c];
            acc8(a0, a1, a2, a3, v, valid ? wn : 0.0f);
        }
    }
    xor_reduce_groups(a0, a1, a2, a3);
    if (g == 0) {
        if (write_dst) dst[row * 8 + c] = pack8(a0, a1, a2, a3);
        store_out(out, r, c, a0, a1, a2, a3, scale);
    }
}

// ---------------- launch ----------------
extern "C" void kernel_launch(void* const* d_in, const int* in_sizes, int n_in,
                              void* d_out, int out_size) {
    const float* user_linear = (const float*)d_in[0];
    const float* item_linear = (const float*)d_in[1];
    const int*   u_idx       = (const int*)d_in[2];
    const int*   i_idx       = (const int*)d_in[3];
    float* out = (float*)d_out;

    int setup_threads = (N_USERS + N_ITEMS) * 8;
    k_setup<<<(setup_threads + 255) / 256, 256>>>(u_idx, user_linear, item_linear);
    k_count<<<(NNZ + 255) / 256, 256>>>(i_idx);
    k_scan1<<<1, 1024>>>();
    // fused: scatter (latency-bound) + user-side embeddings (BW-bound)
    k_scat_embu<<<NB_SCAT + NB_EMBU, 256>>>(u_idx, i_idx, out);
    k_emb_i<<<(N_ITEMS * 32 + 255) / 256, 256>>>(out);

    k_weights<<<(N_USERS * 32 + 255) / 256, 256>>>(i_idx, out);
    k_norm_i<<<(N_ITEMS * 32 + 255) / 256, 256>>>(out);

    k_prop<<<(N_TOTAL * 32 + 255) / 256, 256>>>(out, 1, 1.0f, 1);
    k_prop<<<(N_TOTAL * 32 + 255) / 256, 256>>>(out, 0, 0.25f, 0);
}